// round 1
// baseline (speedup 1.0000x reference)
#include <cuda_runtime.h>
#include <cstdint>
#include <cstdio>

#define B_    16
#define L_    512
#define HID_  1024
#define NH_   16
#define HD_   64
#define M_TOT (B_*L_)      // 8192
#define DCAT  192          // 3*HD concatenated q/k dims

// ---------------- scratch (static device allocations, allowed) ----------------
__device__ float g_Q[(size_t)B_*NH_*L_*DCAT];   // [B][NH][L][192]
__device__ float g_K[(size_t)B_*NH_*L_*DCAT];   // [B][NH][L][192]
__device__ float g_V[(size_t)B_*NH_*L_*HD_];    // [B][NH][L][64]
__device__ float g_att[(size_t)M_TOT*HID_];     // [B*L][HID]

// ---------------- fp32 GEMM: C = X[8192,1024] @ W[1024,1024] + bias ----------------
// mode 0: scatter into [B][NH][L][192] at part*64      (Q/K projections)
// mode 1: scatter into [B][NH][L][64]                  (V projection)
// mode 2: plain row-major [m][n]                       (output projection)
__global__ __launch_bounds__(256)
void gemm_kernel(const float* __restrict__ X, const float* __restrict__ W,
                 const float* __restrict__ bias, float* __restrict__ out,
                 int mode, int part)
{
    __shared__ float As[16][128];   // transposed A tile: As[k][m]
    __shared__ float Bs[16][128];   // Bs[k][n]

    const int m0 = blockIdx.y * 128;
    const int n0 = blockIdx.x * 128;
    const int tid = threadIdx.x;
    const int tx = tid & 15, ty = tid >> 4;

    float acc[8][8];
#pragma unroll
    for (int i = 0; i < 8; i++)
#pragma unroll
        for (int j = 0; j < 8; j++) acc[i][j] = 0.f;

    for (int k0 = 0; k0 < HID_; k0 += 16) {
#pragma unroll
        for (int r = 0; r < 2; r++) {
            int idx = tid + r * 256;           // 0..511 float4 slots (128x16)
            int row = idx >> 2;                // 0..127
            int c4  = (idx & 3) * 4;           // 0..12
            float4 v = *(const float4*)(X + (size_t)(m0 + row) * HID_ + k0 + c4);
            As[c4 + 0][row] = v.x;
            As[c4 + 1][row] = v.y;
            As[c4 + 2][row] = v.z;
            As[c4 + 3][row] = v.w;
        }
#pragma unroll
        for (int r = 0; r < 2; r++) {
            int idx = tid + r * 256;           // 0..511 float4 slots (16x128)
            int row = idx >> 5;                // 0..15
            int c4  = (idx & 31) * 4;          // 0..124
            *(float4*)&Bs[row][c4] =
                *(const float4*)(W + (size_t)(k0 + row) * HID_ + n0 + c4);
        }
        __syncthreads();

#pragma unroll
        for (int kk = 0; kk < 16; kk++) {
            float a[8], b[8];
            *(float4*)&a[0] = *(float4*)&As[kk][ty * 8];
            *(float4*)&a[4] = *(float4*)&As[kk][ty * 8 + 4];
            *(float4*)&b[0] = *(float4*)&Bs[kk][tx * 8];
            *(float4*)&b[4] = *(float4*)&Bs[kk][tx * 8 + 4];
#pragma unroll
            for (int i = 0; i < 8; i++)
#pragma unroll
                for (int j = 0; j < 8; j++)
                    acc[i][j] = fmaf(a[i], b[j], acc[i][j]);
        }
        __syncthreads();
    }

    // epilogue: bias add + layout scatter
    const int n = n0 + tx * 8;
    const int h = n >> 6;
    const int dd = n & 63;
    float bv[8];
#pragma unroll
    for (int j = 0; j < 8; j++) bv[j] = bias[n + j];

#pragma unroll
    for (int i = 0; i < 8; i++) {
        const int m = m0 + ty * 8 + i;
        const int bb = m >> 9;     // m / L_
        const int ll = m & 511;    // m % L_
        size_t base;
        if (mode == 0)
            base = ((((size_t)bb * NH_ + h) * L_ + ll) * DCAT) + (size_t)part * 64 + dd;
        else if (mode == 1)
            base = ((((size_t)bb * NH_ + h) * L_ + ll) * HD_) + dd;
        else
            base = (size_t)m * HID_ + n;
        float o[8];
#pragma unroll
        for (int j = 0; j < 8; j++) o[j] = acc[i][j] + bv[j];
        *(float4*)(out + base)     = *(float4*)&o[0];
        *(float4*)(out + base + 4) = *(float4*)&o[4];
    }
}

// ---------------- flash attention (fp32, causal, +relative_time bias) ----------------
// grid: (qt = 0..7, bh = 0..255), block: 256 threads (16x16), 4x4 micro-tiles.
// smem: Q[64][196] | K^T[192][68] | V[64][68] | P[64][68]  = 137216 bytes
#define QS_STRIDE 196
#define KV_STRIDE 68
#define ATTN_SMEM_BYTES ((64*QS_STRIDE + DCAT*KV_STRIDE + 64*KV_STRIDE + 64*KV_STRIDE) * 4)

__global__ __launch_bounds__(256)
void attn_kernel(const float* __restrict__ rel,
                 const float* __restrict__ Q, const float* __restrict__ K,
                 const float* __restrict__ V, float* __restrict__ out)
{
    extern __shared__ float sm[];
    float* Qs = sm;                            // [64][196]
    float* KT = Qs + 64 * QS_STRIDE;           // [192][68]  (K transposed)
    float* Vs = KT + DCAT * KV_STRIDE;         // [64][68]
    float* Ps = Vs + 64 * KV_STRIDE;           // [64][68]

    const int qt = blockIdx.x;                 // q tile 0..7
    const int bh = blockIdx.y;                 // 0..255
    const int q0 = qt * 64;
    const int tid = threadIdx.x;
    const int tx = tid & 15, ty = tid >> 4;

    const float* Qg   = Q   + (size_t)bh * L_ * DCAT;
    const float* Kg   = K   + (size_t)bh * L_ * DCAT;
    const float* Vg   = V   + (size_t)bh * L_ * HD_;
    const float* relg = rel + (size_t)bh * L_ * L_;

    // load Q tile once
    for (int idx = tid; idx < 64 * 48; idx += 256) {
        int r = idx / 48, c4 = (idx % 48) * 4;
        *(float4*)&Qs[r * QS_STRIDE + c4] =
            *(const float4*)(Qg + (size_t)(q0 + r) * DCAT + c4);
    }

    float m_i[4], l_i[4], O[4][4];
#pragma unroll
    for (int i = 0; i < 4; i++) {
        m_i[i] = -3.0e38f; l_i[i] = 0.f;
#pragma unroll
        for (int j = 0; j < 4; j++) O[i][j] = 0.f;
    }
    const float scale = 0.125f;   // HD^-0.5

    for (int kt = 0; kt <= qt; kt++) {
        const int k0 = kt * 64;
        __syncthreads();   // previous tile's P@V done (also fences Q load on iter 0)

        // load K tile transposed: KT[kk][kcol]
        for (int idx = tid; idx < 64 * 48; idx += 256) {
            int r = idx / 48, c4 = (idx % 48) * 4;
            float4 v = *(const float4*)(Kg + (size_t)(k0 + r) * DCAT + c4);
            KT[(c4 + 0) * KV_STRIDE + r] = v.x;
            KT[(c4 + 1) * KV_STRIDE + r] = v.y;
            KT[(c4 + 2) * KV_STRIDE + r] = v.z;
            KT[(c4 + 3) * KV_STRIDE + r] = v.w;
        }
        // load V tile: Vs[k][d]
        for (int idx = tid; idx < 64 * 16; idx += 256) {
            int r = idx >> 4, c4 = (idx & 15) * 4;
            *(float4*)&Vs[r * KV_STRIDE + c4] =
                *(const float4*)(Vg + (size_t)(k0 + r) * HD_ + c4);
        }
        __syncthreads();

        // S[4][4] = Q(4 rows) . K(4 cols) over 192 dims
        float S[4][4];
#pragma unroll
        for (int i = 0; i < 4; i++)
#pragma unroll
            for (int j = 0; j < 4; j++) S[i][j] = 0.f;

#pragma unroll 2
        for (int kk4 = 0; kk4 < 48; kk4++) {
            float a[4][4];
#pragma unroll
            for (int i = 0; i < 4; i++)
                *(float4*)a[i] = *(const float4*)&Qs[(ty * 4 + i) * QS_STRIDE + kk4 * 4];
#pragma unroll
            for (int c = 0; c < 4; c++) {
                float kv[4];
                *(float4*)kv = *(const float4*)&KT[(kk4 * 4 + c) * KV_STRIDE + tx * 4];
#pragma unroll
                for (int i = 0; i < 4; i++)
#pragma unroll
                    for (int j = 0; j < 4; j++)
                        S[i][j] = fmaf(a[i][c], kv[j], S[i][j]);
            }
        }

        const bool diag = (kt == qt);
#pragma unroll
        for (int i = 0; i < 4; i++) {
            const int qrow = q0 + ty * 4 + i;
            float rr[4];
            *(float4*)rr = *(const float4*)(relg + (size_t)qrow * L_ + k0 + tx * 4);
#pragma unroll
            for (int j = 0; j < 4; j++) {
                float v = fmaf(S[i][j], scale, rr[j]);
                if (diag && (k0 + tx * 4 + j) > qrow) v = -3.0e38f;
                S[i][j] = v;
            }
            // row max across this thread's 4 cols, then across the 16-lane row group
            float tmax = fmaxf(fmaxf(S[i][0], S[i][1]), fmaxf(S[i][2], S[i][3]));
#pragma unroll
            for (int d = 1; d < 16; d <<= 1)
                tmax = fmaxf(tmax, __shfl_xor_sync(0xffffffffu, tmax, d, 16));
            const float mn = fmaxf(m_i[i], tmax);
            const float alpha = __expf(m_i[i] - mn);
            float ts = 0.f;
#pragma unroll
            for (int j = 0; j < 4; j++) {
                S[i][j] = __expf(S[i][j] - mn);
                ts += S[i][j];
            }
#pragma unroll
            for (int d = 1; d < 16; d <<= 1)
                ts += __shfl_xor_sync(0xffffffffu, ts, d, 16);
            l_i[i] = l_i[i] * alpha + ts;
            m_i[i] = mn;
#pragma unroll
            for (int j = 0; j < 4; j++) O[i][j] *= alpha;
            *(float4*)&Ps[(ty * 4 + i) * KV_STRIDE + tx * 4] = *(float4*)S[i];
        }
        __syncthreads();

        // O += P @ V   (64x64 x 64)
#pragma unroll 2
        for (int kk4 = 0; kk4 < 16; kk4++) {
            float p[4][4];
#pragma unroll
            for (int i = 0; i < 4; i++)
                *(float4*)p[i] = *(const float4*)&Ps[(ty * 4 + i) * KV_STRIDE + kk4 * 4];
#pragma unroll
            for (int c = 0; c < 4; c++) {
                float vv[4];
                *(float4*)vv = *(const float4*)&Vs[(kk4 * 4 + c) * KV_STRIDE + tx * 4];
#pragma unroll
                for (int i = 0; i < 4; i++)
#pragma unroll
                    for (int j = 0; j < 4; j++)
                        O[i][j] = fmaf(p[i][c], vv[j], O[i][j]);
            }
        }
    }

    // epilogue: normalize and write [b*L + q][h*64 + d]
    const int b = bh >> 4, h = bh & 15;
#pragma unroll
    for (int i = 0; i < 4; i++) {
        const float inv = 1.0f / l_i[i];
        float o[4];
#pragma unroll
        for (int j = 0; j < 4; j++) o[j] = O[i][j] * inv;
        size_t off = ((size_t)(b * L_ + q0 + ty * 4 + i)) * HID_ + h * 64 + tx * 4;
        *(float4*)(out + off) = *(float4*)o;
    }
}

// ---------------- launcher ----------------
extern "C" void kernel_launch(void* const* d_in, const int* in_sizes, int n_in,
                              void* d_out, int out_size)
{
    const float* seq_id   = (const float*)d_in[0];
    const float* seq_cate = (const float*)d_in[1];
    const float* seq_pos  = (const float*)d_in[2];
    const float* Vin      = (const float*)d_in[3];
    // d_in[4] = attn_mask (always causal tril; handled analytically)
    const float* rel      = (const float*)d_in[5];
    const float* q_id_w   = (const float*)d_in[6];
    const float* q_id_b   = (const float*)d_in[7];
    const float* k_id_w   = (const float*)d_in[8];
    const float* k_id_b   = (const float*)d_in[9];
    const float* v_id_w   = (const float*)d_in[10];
    const float* v_id_b   = (const float*)d_in[11];
    const float* q_cate_w = (const float*)d_in[12];
    const float* q_cate_b = (const float*)d_in[13];
    const float* k_cate_w = (const float*)d_in[14];
    const float* k_cate_b = (const float*)d_in[15];
    const float* q_pos_w  = (const float*)d_in[16];
    const float* q_pos_b  = (const float*)d_in[17];
    const float* k_pos_w  = (const float*)d_in[18];
    const float* k_pos_b  = (const float*)d_in[19];
    const float* out_w    = (const float*)d_in[20];
    const float* out_b    = (const float*)d_in[21];
    float* out = (float*)d_out;

    float *Qb, *Kb, *Vb, *Ab;
    cudaGetSymbolAddress((void**)&Qb, g_Q);
    cudaGetSymbolAddress((void**)&Kb, g_K);
    cudaGetSymbolAddress((void**)&Vb, g_V);
    cudaGetSymbolAddress((void**)&Ab, g_att);

    cudaFuncSetAttribute(attn_kernel, cudaFuncAttributeMaxDynamicSharedMemorySize,
                         ATTN_SMEM_BYTES);

    dim3 ggrid(HID_ / 128, M_TOT / 128);   // (8, 64)

    // 7 projection GEMMs -> head-major scratch
    gemm_kernel<<<ggrid, 256>>>(seq_id,   q_id_w,   q_id_b,   Qb, 0, 0);
    gemm_kernel<<<ggrid, 256>>>(seq_cate, q_cate_w, q_cate_b, Qb, 0, 1);
    gemm_kernel<<<ggrid, 256>>>(seq_pos,  q_pos_w,  q_pos_b,  Qb, 0, 2);
    gemm_kernel<<<ggrid, 256>>>(seq_id,   k_id_w,   k_id_b,   Kb, 0, 0);
    gemm_kernel<<<ggrid, 256>>>(seq_cate, k_cate_w, k_cate_b, Kb, 0, 1);
    gemm_kernel<<<ggrid, 256>>>(seq_pos,  k_pos_w,  k_pos_b,  Kb, 0, 2);
    gemm_kernel<<<ggrid, 256>>>(Vin,      v_id_w,   v_id_b,   Vb, 1, 0);

    // fused causal attention with relative_time bias
    attn_kernel<<<dim3(L_ / 64, B_ * NH_), 256, ATTN_SMEM_BYTES>>>(rel, Qb, Kb, Vb, Ab);

    // output projection -> d_out
    gemm_kernel<<<ggrid, 256>>>(Ab, out_w, out_b, out, 2, 0);
}

// round 3
// speedup vs baseline: 1.8514x; 1.8514x over previous
#include <cuda_runtime.h>
#include <cuda_bf16.h>
#include <cstdint>
#include <cstdio>

#define B_    16
#define L_    512
#define HID_  1024
#define NH_   16
#define HD_   64
#define M_TOT (B_*L_)      // 8192
#define DCAT  192          // 3*HD concatenated q/k dims

// ---------------- scratch (static device arrays — no runtime allocs) ----------------
__device__ float g_Q[(size_t)B_*NH_*L_*DCAT];            // [B][NH][L][192]
__device__ float g_K[(size_t)B_*NH_*L_*DCAT];            // [B][NH][L][192]
__device__ float g_V[(size_t)B_*NH_*L_*HD_];             // [B][NH][L][64]
__device__ float g_att[(size_t)M_TOT*HID_];              // [B*L][HID]
__device__ __nv_bfloat16 g_xh[5ULL*M_TOT*HID_];          // hi halves: 4 inputs + attn-out
__device__ __nv_bfloat16 g_xl[5ULL*M_TOT*HID_];          // lo halves
__device__ __nv_bfloat16 g_wh[8ULL*HID_*HID_];           // W^T hi (8 weights)
__device__ __nv_bfloat16 g_wl[8ULL*HID_*HID_];           // W^T lo

// ---------------- PTX helpers (baseline ISA only — no 'a' features) ----------------
__device__ __forceinline__ uint32_t smem_u32(const void* p) {
    uint32_t a;
    asm("{ .reg .u64 t; cvta.to.shared.u64 t, %1; cvt.u32.u64 %0, t; }" : "=r"(a) : "l"(p));
    return a;
}
__device__ __forceinline__ void cp16(uint32_t dst, const void* src) {
    asm volatile("cp.async.cg.shared.global [%0], [%1], 16;" :: "r"(dst), "l"(src));
}
__device__ __forceinline__ void ldm_x4(uint32_t* r, uint32_t addr) {
    asm volatile("ldmatrix.sync.aligned.m8n8.x4.shared.b16 {%0,%1,%2,%3}, [%4];"
                 : "=r"(r[0]), "=r"(r[1]), "=r"(r[2]), "=r"(r[3]) : "r"(addr));
}
__device__ __forceinline__ void mma16816(float* d, const uint32_t* a, const uint32_t* b) {
    asm volatile(
        "mma.sync.aligned.m16n8k16.row.col.f32.bf16.bf16.f32 "
        "{%0,%1,%2,%3}, {%4,%5,%6,%7}, {%8,%9}, {%0,%1,%2,%3};"
        : "+f"(d[0]), "+f"(d[1]), "+f"(d[2]), "+f"(d[3])
        : "r"(a[0]), "r"(a[1]), "r"(a[2]), "r"(a[3]), "r"(b[0]), "r"(b[1]));
}

// ---------------- fp32 -> split bf16 (elementwise) ----------------
__global__ __launch_bounds__(256)
void split_f32(const float* __restrict__ src, __nv_bfloat16* __restrict__ hi,
               __nv_bfloat16* __restrict__ lo, int n4)
{
    int i = blockIdx.x * blockDim.x + threadIdx.x;
    if (i >= n4) return;
    float4 v = ((const float4*)src)[i];
    __nv_bfloat16 h0 = __float2bfloat16(v.x);
    __nv_bfloat16 h1 = __float2bfloat16(v.y);
    __nv_bfloat16 h2 = __float2bfloat16(v.z);
    __nv_bfloat16 h3 = __float2bfloat16(v.w);
    __nv_bfloat162 hh0; hh0.x = h0; hh0.y = h1;
    __nv_bfloat162 hh1; hh1.x = h2; hh1.y = h3;
    __nv_bfloat162 ll0, ll1;
    ll0.x = __float2bfloat16(v.x - __bfloat162float(h0));
    ll0.y = __float2bfloat16(v.y - __bfloat162float(h1));
    ll1.x = __float2bfloat16(v.z - __bfloat162float(h2));
    ll1.y = __float2bfloat16(v.w - __bfloat162float(h3));
    ((__nv_bfloat162*)hi)[i * 2]     = hh0;
    ((__nv_bfloat162*)hi)[i * 2 + 1] = hh1;
    ((__nv_bfloat162*)lo)[i * 2]     = ll0;
    ((__nv_bfloat162*)lo)[i * 2 + 1] = ll1;
}

// ---------------- W[k][n] -> W^T[n][k] split bf16 ----------------
__global__ __launch_bounds__(256)
void splitT_f32(const float* __restrict__ W, __nv_bfloat16* __restrict__ hiT,
                __nv_bfloat16* __restrict__ loT)
{
    __shared__ float t[32][33];
    int bx = blockIdx.x * 32;   // n block
    int by = blockIdx.y * 32;   // k block
    int tx = threadIdx.x, ty = threadIdx.y;   // 32 x 8
#pragma unroll
    for (int j = 0; j < 4; j++)
        t[ty + 8 * j][tx] = W[(size_t)(by + ty + 8 * j) * HID_ + bx + tx];
    __syncthreads();
#pragma unroll
    for (int j = 0; j < 4; j++) {
        float v = t[tx][ty + 8 * j];   // W[by+tx][bx+ty+8j]
        int n = bx + ty + 8 * j, k = by + tx;
        __nv_bfloat16 h = __float2bfloat16(v);
        hiT[(size_t)n * HID_ + k] = h;
        loT[(size_t)n * HID_ + k] = __float2bfloat16(v - __bfloat162float(h));
    }
}

// ---------------- mma.sync split-bf16 GEMM ----------------
// C[8192,1024] = X @ W + bias, X = Xh + Xl, W^T pre-split.
// K concat: 48 chunks of 64 -> phases (Ah,Bh),(Ah,Bl),(Al,Bh).
// CTA tile 128x128, 8 warps (4m x 2n), warp tile 32x64, double-buffered cp.async.
#define KC        64
#define NCHUNK    48
#define ROWB      144u            // padded row stride in bytes (64 bf16 = 128B data)
#define ATILE_B   (128u*ROWB)     // 18432
#define STAGE_B   (2u*ATILE_B)    // 36864 (A + B)
#define GEMM_SMEM (2*STAGE_B)     // 73728

__device__ __forceinline__ void gemm_load_tile(
    uint32_t sbase, int s, int c, int m0, int n0, int tid,
    const __nv_bfloat16* __restrict__ Ah, const __nv_bfloat16* __restrict__ Al,
    const __nv_bfloat16* __restrict__ Bh, const __nv_bfloat16* __restrict__ Bl)
{
    const __nv_bfloat16* asrc = (c < 32) ? Ah : Al;
    const __nv_bfloat16* bsrc = (c < 16) ? Bh : ((c < 32) ? Bl : Bh);
    const int k0 = (c & 15) * KC;
    const uint32_t dstA = sbase + (uint32_t)s * STAGE_B;
    const uint32_t dstB = dstA + ATILE_B;
#pragma unroll
    for (int i = 0; i < 8; i++) {
        int idx = i * 256 + tid;            // 0..2047 16B segments
        int r = (idx >> 3) & 127, c16 = idx & 7;
        if (idx < 1024)
            cp16(dstA + r * ROWB + c16 * 16,
                 asrc + (size_t)(m0 + r) * HID_ + k0 + c16 * 8);
        else
            cp16(dstB + r * ROWB + c16 * 16,
                 bsrc + (size_t)(n0 + r) * HID_ + k0 + c16 * 8);
    }
    asm volatile("cp.async.commit_group;");
}

__global__ __launch_bounds__(256, 2)
void gemm_mma(const __nv_bfloat16* __restrict__ Ah, const __nv_bfloat16* __restrict__ Al,
              const __nv_bfloat16* __restrict__ Bh, const __nv_bfloat16* __restrict__ Bl,
              const float* __restrict__ bias, float* __restrict__ out, int mode, int part)
{
    extern __shared__ char smem[];
    const uint32_t sbase = smem_u32(smem);
    const int tid = threadIdx.x;
    const int wid = tid >> 5, lane = tid & 31;
    const int m0 = blockIdx.y * 128;
    const int n0 = blockIdx.x * 128;
    const int wm = wid & 3, wn = wid >> 2;   // warp tile: rows wm*32, cols wn*64

    float acc[2][8][4];
#pragma unroll
    for (int mf = 0; mf < 2; mf++)
#pragma unroll
        for (int nf = 0; nf < 8; nf++)
#pragma unroll
            for (int q = 0; q < 4; q++) acc[mf][nf][q] = 0.f;

    // ldmatrix lane base offsets (bytes within tile)
    const int arow = wm * 32 + (lane & 7) + ((lane >> 3) & 1) * 8;
    const uint32_t a_l = (uint32_t)arow * ROWB + ((lane >> 4) * 16);
    const int brow = wn * 64 + (lane & 7) + ((lane >> 4) & 1) * 8;
    const uint32_t b_l = (uint32_t)brow * ROWB + (((lane >> 3) & 1) * 16);

    gemm_load_tile(sbase, 0, 0, m0, n0, tid, Ah, Al, Bh, Bl);

    for (int c = 0; c < NCHUNK; c++) {
        const int s = c & 1;
        if (c + 1 < NCHUNK) {
            gemm_load_tile(sbase, (c + 1) & 1, c + 1, m0, n0, tid, Ah, Al, Bh, Bl);
            asm volatile("cp.async.wait_group 1;" ::: "memory");
        } else {
            asm volatile("cp.async.wait_group 0;" ::: "memory");
        }
        __syncthreads();

        const uint32_t aBase = sbase + (uint32_t)s * STAGE_B + a_l;
        const uint32_t bBase = sbase + (uint32_t)s * STAGE_B + ATILE_B + b_l;
#pragma unroll
        for (int kk = 0; kk < KC / 16; kk++) {
            const uint32_t koff = kk * 32;   // 16 halves = 32 bytes
            uint32_t bq[16];
#pragma unroll
            for (int np = 0; np < 4; np++)
                ldm_x4(&bq[np * 4], bBase + np * 16 * ROWB + koff);
            uint32_t aq[2][4];
#pragma unroll
            for (int mf = 0; mf < 2; mf++)
                ldm_x4(aq[mf], aBase + mf * 16 * ROWB + koff);
#pragma unroll
            for (int mf = 0; mf < 2; mf++)
#pragma unroll
                for (int nf = 0; nf < 8; nf++)
                    mma16816(acc[mf][nf], aq[mf], &bq[(nf >> 1) * 4 + (nf & 1) * 2]);
        }
        __syncthreads();
    }

    // epilogue: bias + layout scatter, direct float2 stores
    const int g = lane >> 2, tq = lane & 3;
    float2 bv[8];
#pragma unroll
    for (int nf = 0; nf < 8; nf++) {
        int n = n0 + wn * 64 + nf * 8 + 2 * tq;
        bv[nf] = *(const float2*)(bias + n);
    }
#pragma unroll
    for (int mf = 0; mf < 2; mf++) {
#pragma unroll
        for (int half = 0; half < 2; half++) {
            const int m = m0 + wm * 32 + mf * 16 + g + half * 8;
            const int bb = m >> 9, ll = m & 511;
#pragma unroll
            for (int nf = 0; nf < 8; nf++) {
                const int n = n0 + wn * 64 + nf * 8 + 2 * tq;
                size_t dst;
                if (mode == 0) {
                    int h = n >> 6, dd = n & 63;
                    dst = ((((size_t)bb * NH_ + h) * L_ + ll) * DCAT) + (size_t)part * 64 + dd;
                } else if (mode == 1) {
                    int h = n >> 6, dd = n & 63;
                    dst = ((((size_t)bb * NH_ + h) * L_ + ll) * HD_) + dd;
                } else {
                    dst = (size_t)m * HID_ + n;
                }
                float2 v;
                v.x = acc[mf][nf][half * 2 + 0] + bv[nf].x;
                v.y = acc[mf][nf][half * 2 + 1] + bv[nf].y;
                *(float2*)(out + dst) = v;
            }
        }
    }
}

// ---------------- flash attention (fp32, causal, +relative_time bias) ----------------
#define QS_STRIDE 196
#define KV_STRIDE 68
#define ATTN_SMEM_BYTES ((64*QS_STRIDE + DCAT*KV_STRIDE + 64*KV_STRIDE + 64*KV_STRIDE) * 4)

__global__ __launch_bounds__(256)
void attn_kernel(const float* __restrict__ rel,
                 const float* __restrict__ Q, const float* __restrict__ K,
                 const float* __restrict__ V, float* __restrict__ out)
{
    extern __shared__ float sm[];
    float* Qs = sm;
    float* KT = Qs + 64 * QS_STRIDE;
    float* Vs = KT + DCAT * KV_STRIDE;
    float* Ps = Vs + 64 * KV_STRIDE;

    const int qt = blockIdx.x;
    const int bh = blockIdx.y;
    const int q0 = qt * 64;
    const int tid = threadIdx.x;
    const int tx = tid & 15, ty = tid >> 4;

    const float* Qg   = Q   + (size_t)bh * L_ * DCAT;
    const float* Kg   = K   + (size_t)bh * L_ * DCAT;
    const float* Vg   = V   + (size_t)bh * L_ * HD_;
    const float* relg = rel + (size_t)bh * L_ * L_;

    for (int idx = tid; idx < 64 * 48; idx += 256) {
        int r = idx / 48, c4 = (idx % 48) * 4;
        *(float4*)&Qs[r * QS_STRIDE + c4] =
            *(const float4*)(Qg + (size_t)(q0 + r) * DCAT + c4);
    }

    float m_i[4], l_i[4], O[4][4];
#pragma unroll
    for (int i = 0; i < 4; i++) {
        m_i[i] = -3.0e38f; l_i[i] = 0.f;
#pragma unroll
        for (int j = 0; j < 4; j++) O[i][j] = 0.f;
    }
    const float scale = 0.125f;

    for (int kt = 0; kt <= qt; kt++) {
        const int k0 = kt * 64;
        __syncthreads();

        for (int idx = tid; idx < 64 * 48; idx += 256) {
            int r = idx / 48, c4 = (idx % 48) * 4;
            float4 v = *(const float4*)(Kg + (size_t)(k0 + r) * DCAT + c4);
            KT[(c4 + 0) * KV_STRIDE + r] = v.x;
            KT[(c4 + 1) * KV_STRIDE + r] = v.y;
            KT[(c4 + 2) * KV_STRIDE + r] = v.z;
            KT[(c4 + 3) * KV_STRIDE + r] = v.w;
        }
        for (int idx = tid; idx < 64 * 16; idx += 256) {
            int r = idx >> 4, c4 = (idx & 15) * 4;
            *(float4*)&Vs[r * KV_STRIDE + c4] =
                *(const float4*)(Vg + (size_t)(k0 + r) * HD_ + c4);
        }
        __syncthreads();

        float S[4][4];
#pragma unroll
        for (int i = 0; i < 4; i++)
#pragma unroll
            for (int j = 0; j < 4; j++) S[i][j] = 0.f;

#pragma unroll 2
        for (int kk4 = 0; kk4 < 48; kk4++) {
            float a[4][4];
#pragma unroll
            for (int i = 0; i < 4; i++)
                *(float4*)a[i] = *(const float4*)&Qs[(ty * 4 + i) * QS_STRIDE + kk4 * 4];
#pragma unroll
            for (int cc = 0; cc < 4; cc++) {
                float kv[4];
                *(float4*)kv = *(const float4*)&KT[(kk4 * 4 + cc) * KV_STRIDE + tx * 4];
#pragma unroll
                for (int i = 0; i < 4; i++)
#pragma unroll
                    for (int j = 0; j < 4; j++)
                        S[i][j] = fmaf(a[i][cc], kv[j], S[i][j]);
            }
        }

        const bool diag = (kt == qt);
#pragma unroll
        for (int i = 0; i < 4; i++) {
            const int qrow = q0 + ty * 4 + i;
            float rr[4];
            *(float4*)rr = *(const float4*)(relg + (size_t)qrow * L_ + k0 + tx * 4);
#pragma unroll
            for (int j = 0; j < 4; j++) {
                float v = fmaf(S[i][j], scale, rr[j]);
                if (diag && (k0 + tx * 4 + j) > qrow) v = -3.0e38f;
                S[i][j] = v;
            }
            float tmax = fmaxf(fmaxf(S[i][0], S[i][1]), fmaxf(S[i][2], S[i][3]));
#pragma unroll
            for (int d = 1; d < 16; d <<= 1)
                tmax = fmaxf(tmax, __shfl_xor_sync(0xffffffffu, tmax, d, 16));
            const float mn = fmaxf(m_i[i], tmax);
            const float alpha = __expf(m_i[i] - mn);
            float ts = 0.f;
#pragma unroll
            for (int j = 0; j < 4; j++) {
                S[i][j] = __expf(S[i][j] - mn);
                ts += S[i][j];
            }
#pragma unroll
            for (int d = 1; d < 16; d <<= 1)
                ts += __shfl_xor_sync(0xffffffffu, ts, d, 16);
            l_i[i] = l_i[i] * alpha + ts;
            m_i[i] = mn;
#pragma unroll
            for (int j = 0; j < 4; j++) O[i][j] *= alpha;
            *(float4*)&Ps[(ty * 4 + i) * KV_STRIDE + tx * 4] = *(float4*)S[i];
        }
        __syncthreads();

#pragma unroll 2
        for (int kk4 = 0; kk4 < 16; kk4++) {
            float p[4][4];
#pragma unroll
            for (int i = 0; i < 4; i++)
                *(float4*)p[i] = *(const float4*)&Ps[(ty * 4 + i) * KV_STRIDE + kk4 * 4];
#pragma unroll
            for (int cc = 0; cc < 4; cc++) {
                float vv[4];
                *(float4*)vv = *(const float4*)&Vs[(kk4 * 4 + cc) * KV_STRIDE + tx * 4];
#pragma unroll
                for (int i = 0; i < 4; i++)
#pragma unroll
                    for (int j = 0; j < 4; j++)
                        O[i][j] = fmaf(p[i][cc], vv[j], O[i][j]);
            }
        }
    }

    const int b = bh >> 4, h = bh & 15;
#pragma unroll
    for (int i = 0; i < 4; i++) {
        const float inv = 1.0f / l_i[i];
        float o[4];
#pragma unroll
        for (int j = 0; j < 4; j++) o[j] = O[i][j] * inv;
        size_t off = ((size_t)(b * L_ + q0 + ty * 4 + i)) * HID_ + h * 64 + tx * 4;
        *(float4*)(out + off) = *(float4*)o;
    }
}

// ---------------- launcher ----------------
extern "C" void kernel_launch(void* const* d_in, const int* in_sizes, int n_in,
                              void* d_out, int out_size)
{
    const float* X[4]  = { (const float*)d_in[0], (const float*)d_in[1],
                           (const float*)d_in[2], (const float*)d_in[3] };
    const float* rel   = (const float*)d_in[5];
    const float* W[8]  = { (const float*)d_in[6],  (const float*)d_in[8],
                           (const float*)d_in[10], (const float*)d_in[12],
                           (const float*)d_in[14], (const float*)d_in[16],
                           (const float*)d_in[18], (const float*)d_in[20] };
    const float* bias_q_id   = (const float*)d_in[7];
    const float* bias_k_id   = (const float*)d_in[9];
    const float* bias_v_id   = (const float*)d_in[11];
    const float* bias_q_cate = (const float*)d_in[13];
    const float* bias_k_cate = (const float*)d_in[15];
    const float* bias_q_pos  = (const float*)d_in[17];
    const float* bias_k_pos  = (const float*)d_in[19];
    const float* bias_out    = (const float*)d_in[21];
    float* out = (float*)d_out;

    float *Qb, *Kb, *Vb, *Ab;
    __nv_bfloat16 *xh, *xl, *wh, *wl;
    cudaGetSymbolAddress((void**)&Qb, g_Q);
    cudaGetSymbolAddress((void**)&Kb, g_K);
    cudaGetSymbolAddress((void**)&Vb, g_V);
    cudaGetSymbolAddress((void**)&Ab, g_att);
    cudaGetSymbolAddress((void**)&xh, g_xh);
    cudaGetSymbolAddress((void**)&xl, g_xl);
    cudaGetSymbolAddress((void**)&wh, g_wh);
    cudaGetSymbolAddress((void**)&wl, g_wl);

    cudaFuncSetAttribute(attn_kernel, cudaFuncAttributeMaxDynamicSharedMemorySize,
                         ATTN_SMEM_BYTES);
    cudaFuncSetAttribute(gemm_mma, cudaFuncAttributeMaxDynamicSharedMemorySize,
                         GEMM_SMEM);

    const size_t XN = (size_t)M_TOT * HID_;
    const size_t WN = (size_t)HID_ * HID_;
    const int n4 = (int)(XN / 4);

    for (int i = 0; i < 4; i++)
        split_f32<<<(n4 + 255) / 256, 256>>>(X[i], xh + i * XN, xl + i * XN, n4);
    for (int i = 0; i < 8; i++)
        splitT_f32<<<dim3(32, 32), dim3(32, 8)>>>(W[i], wh + i * WN, wl + i * WN);

    dim3 ggrid(HID_ / 128, M_TOT / 128);   // (8, 64)
    // W slot order: 0=q_id 1=k_id 2=v_id 3=q_cate 4=k_cate 5=q_pos 6=k_pos 7=out
    gemm_mma<<<ggrid, 256, GEMM_SMEM>>>(xh + 0*XN, xl + 0*XN, wh + 0*WN, wl + 0*WN, bias_q_id,   Qb, 0, 0);
    gemm_mma<<<ggrid, 256, GEMM_SMEM>>>(xh + 1*XN, xl + 1*XN, wh + 3*WN, wl + 3*WN, bias_q_cate, Qb, 0, 1);
    gemm_mma<<<ggrid, 256, GEMM_SMEM>>>(xh + 2*XN, xl + 2*XN, wh + 5*WN, wl + 5*WN, bias_q_pos,  Qb, 0, 2);
    gemm_mma<<<ggrid, 256, GEMM_SMEM>>>(xh + 0*XN, xl + 0*XN, wh + 1*WN, wl + 1*WN, bias_k_id,   Kb, 0, 0);
    gemm_mma<<<ggrid, 256, GEMM_SMEM>>>(xh + 1*XN, xl + 1*XN, wh + 4*WN, wl + 4*WN, bias_k_cate, Kb, 0, 1);
    gemm_mma<<<ggrid, 256, GEMM_SMEM>>>(xh + 2*XN, xl + 2*XN, wh + 6*WN, wl + 6*WN, bias_k_pos,  Kb, 0, 2);
    gemm_mma<<<ggrid, 256, GEMM_SMEM>>>(xh + 3*XN, xl + 3*XN, wh + 2*WN, wl + 2*WN, bias_v_id,   Vb, 1, 0);

    attn_kernel<<<dim3(L_ / 64, B_ * NH_), 256, ATTN_SMEM_BYTES>>>(rel, Qb, Kb, Vb, Ab);

    split_f32<<<(n4 + 255) / 256, 256>>>(Ab, xh + 4 * XN, xl + 4 * XN, n4);
    gemm_mma<<<ggrid, 256, GEMM_SMEM>>>(xh + 4*XN, xl + 4*XN, wh + 7*WN, wl + 7*WN, bias_out, out, 2, 0);
}

// round 4
// speedup vs baseline: 2.9300x; 1.5826x over previous
#include <cuda_runtime.h>
#include <cuda_bf16.h>
#include <cstdint>

#define B_    16
#define L_    512
#define HID_  1024
#define NH_   16
#define HD_   64
#define M_TOT (B_*L_)      // 8192
#define DCAT  192
#define XN    ((size_t)M_TOT*HID_)
#define WN    ((size_t)HID_*HID_)

// ---------------- scratch (static device arrays) ----------------
__device__ __nv_bfloat16 g_xh[5ULL*XN];     // 4 inputs + attn-out (hi)
__device__ __nv_bfloat16 g_xl[5ULL*XN];     // lo
__device__ __nv_bfloat16 g_wh[8ULL*WN];     // W^T hi
__device__ __nv_bfloat16 g_wl[8ULL*WN];     // W^T lo
__device__ __nv_bfloat16 g_qh[(size_t)B_*NH_*L_*DCAT];
__device__ __nv_bfloat16 g_ql[(size_t)B_*NH_*L_*DCAT];
__device__ __nv_bfloat16 g_kh[(size_t)B_*NH_*L_*DCAT];
__device__ __nv_bfloat16 g_kl[(size_t)B_*NH_*L_*DCAT];
__device__ __nv_bfloat16 g_vth[(size_t)B_*NH_*HD_*L_];   // V transposed [bh][d][l]
__device__ __nv_bfloat16 g_vtl[(size_t)B_*NH_*HD_*L_];

// ---------------- PTX helpers (baseline ISA only) ----------------
__device__ __forceinline__ uint32_t smem_u32(const void* p) {
    uint32_t a;
    asm("{ .reg .u64 t; cvta.to.shared.u64 t, %1; cvt.u32.u64 %0, t; }" : "=r"(a) : "l"(p));
    return a;
}
__device__ __forceinline__ void cp16(uint32_t dst, const void* src) {
    asm volatile("cp.async.cg.shared.global [%0], [%1], 16;" :: "r"(dst), "l"(src));
}
__device__ __forceinline__ void ldm_x4(uint32_t* r, uint32_t addr) {
    asm volatile("ldmatrix.sync.aligned.m8n8.x4.shared.b16 {%0,%1,%2,%3}, [%4];"
                 : "=r"(r[0]), "=r"(r[1]), "=r"(r[2]), "=r"(r[3]) : "r"(addr));
}
__device__ __forceinline__ void mma16816(float* d, const uint32_t* a, const uint32_t* b) {
    asm volatile(
        "mma.sync.aligned.m16n8k16.row.col.f32.bf16.bf16.f32 "
        "{%0,%1,%2,%3}, {%4,%5,%6,%7}, {%8,%9}, {%0,%1,%2,%3};"
        : "+f"(d[0]), "+f"(d[1]), "+f"(d[2]), "+f"(d[3])
        : "r"(a[0]), "r"(a[1]), "r"(a[2]), "r"(a[3]), "r"(b[0]), "r"(b[1]));
}
__device__ __forceinline__ uint32_t pack_bf2(float a, float b) {
    __nv_bfloat162 t;
    t.x = __float2bfloat16(a); t.y = __float2bfloat16(b);
    return *(uint32_t*)&t;
}

// ---------------- batched fp32 -> split bf16 ----------------
struct SplitSrc { const float* p[4]; };
__global__ __launch_bounds__(256)
void split_b(SplitSrc s, __nv_bfloat16* __restrict__ hi, __nv_bfloat16* __restrict__ lo, int n4)
{
    int i = blockIdx.x * 256 + threadIdx.x;
    if (i >= n4) return;
    int z = blockIdx.y;
    const float* src = s.p[z];
    __nv_bfloat16* hz = hi + (size_t)z * XN;
    __nv_bfloat16* lz = lo + (size_t)z * XN;
    float4 v = ((const float4*)src)[i];
    __nv_bfloat16 h0 = __float2bfloat16(v.x), h1 = __float2bfloat16(v.y);
    __nv_bfloat16 h2 = __float2bfloat16(v.z), h3 = __float2bfloat16(v.w);
    __nv_bfloat162 hh0{h0, h1}, hh1{h2, h3};
    __nv_bfloat162 ll0, ll1;
    ll0.x = __float2bfloat16(v.x - __bfloat162float(h0));
    ll0.y = __float2bfloat16(v.y - __bfloat162float(h1));
    ll1.x = __float2bfloat16(v.z - __bfloat162float(h2));
    ll1.y = __float2bfloat16(v.w - __bfloat162float(h3));
    ((__nv_bfloat162*)hz)[i*2] = hh0;  ((__nv_bfloat162*)hz)[i*2+1] = hh1;
    ((__nv_bfloat162*)lz)[i*2] = ll0;  ((__nv_bfloat162*)lz)[i*2+1] = ll1;
}

// ---------------- batched W[k][n] -> W^T[n][k] split ----------------
struct WSrc { const float* p[8]; };
__global__ __launch_bounds__(256)
void splitT_b(WSrc s, __nv_bfloat16* __restrict__ hiT, __nv_bfloat16* __restrict__ loT)
{
    __shared__ float t[32][33];
    int z = blockIdx.z;
    const float* W = s.p[z];
    __nv_bfloat16* hz = hiT + (size_t)z * WN;
    __nv_bfloat16* lz = loT + (size_t)z * WN;
    int bx = blockIdx.x * 32, by = blockIdx.y * 32;
    int tx = threadIdx.x, ty = threadIdx.y;
#pragma unroll
    for (int j = 0; j < 4; j++)
        t[ty + 8*j][tx] = W[(size_t)(by + ty + 8*j) * HID_ + bx + tx];
    __syncthreads();
#pragma unroll
    for (int j = 0; j < 4; j++) {
        float v = t[tx][ty + 8*j];
        int n = bx + ty + 8*j, k = by + tx;
        __nv_bfloat16 h = __float2bfloat16(v);
        hz[(size_t)n * HID_ + k] = h;
        lz[(size_t)n * HID_ + k] = __float2bfloat16(v - __bfloat162float(h));
    }
}

// ---------------- GEMM core: 3-stage cp.async + mma.sync ----------------
#define KC        64
#define NCHUNK    48
#define ROWB      144u
#define ATILE_B   (128u*ROWB)
#define STAGE_B   (2u*ATILE_B)          // 36864
#define GEMM_SMEM (3*STAGE_B)           // 110592

__device__ __forceinline__ void gemm_load_tile(
    uint32_t sbase, int stage, int c, int m0, int n0, int tid,
    const __nv_bfloat16* Ah, const __nv_bfloat16* Al,
    const __nv_bfloat16* Bh, const __nv_bfloat16* Bl)
{
    const __nv_bfloat16* asrc = (c < 32) ? Ah : Al;
    const __nv_bfloat16* bsrc = (c < 16) ? Bh : ((c < 32) ? Bl : Bh);
    const int k0 = (c & 15) * KC;
    const uint32_t dstA = sbase + (uint32_t)stage * STAGE_B;
    const uint32_t dstB = dstA + ATILE_B;
#pragma unroll
    for (int i = 0; i < 8; i++) {
        int idx = i * 256 + tid;
        int r = (idx >> 3) & 127, c16 = idx & 7;
        if (idx < 1024)
            cp16(dstA + r * ROWB + c16 * 16, asrc + (size_t)(m0 + r) * HID_ + k0 + c16 * 8);
        else
            cp16(dstB + r * ROWB + c16 * 16, bsrc + (size_t)(n0 + r) * HID_ + k0 + c16 * 8);
    }
    asm volatile("cp.async.commit_group;");
}

__device__ __forceinline__ void gemm_core(
    uint32_t sbase, int m0, int n0, int tid, int wm, int wn, int lane,
    const __nv_bfloat16* Ah, const __nv_bfloat16* Al,
    const __nv_bfloat16* Bh, const __nv_bfloat16* Bl,
    float acc[2][8][4])
{
    const int arow = wm * 32 + (lane & 7) + ((lane >> 3) & 1) * 8;
    const uint32_t a_l = (uint32_t)arow * ROWB + ((lane >> 4) * 16);
    const int brow = wn * 64 + (lane & 7) + ((lane >> 4) & 1) * 8;
    const uint32_t b_l = (uint32_t)brow * ROWB + (((lane >> 3) & 1) * 16);

    gemm_load_tile(sbase, 0, 0, m0, n0, tid, Ah, Al, Bh, Bl);
    gemm_load_tile(sbase, 1, 1, m0, n0, tid, Ah, Al, Bh, Bl);

    for (int c = 0; c < NCHUNK; c++) {
        if (c < NCHUNK - 1) asm volatile("cp.async.wait_group 1;" ::: "memory");
        else                asm volatile("cp.async.wait_group 0;" ::: "memory");
        __syncthreads();
        if (c + 2 < NCHUNK)
            gemm_load_tile(sbase, (c + 2) % 3, c + 2, m0, n0, tid, Ah, Al, Bh, Bl);

        const uint32_t sb = sbase + (uint32_t)(c % 3) * STAGE_B;
        const uint32_t aBase = sb + a_l;
        const uint32_t bBase = sb + ATILE_B + b_l;
#pragma unroll
        for (int kk = 0; kk < KC / 16; kk++) {
            const uint32_t koff = kk * 32;
            uint32_t bq[16];
#pragma unroll
            for (int np = 0; np < 4; np++)
                ldm_x4(&bq[np * 4], bBase + np * 16 * ROWB + koff);
            uint32_t aq[2][4];
#pragma unroll
            for (int mf = 0; mf < 2; mf++)
                ldm_x4(aq[mf], aBase + mf * 16 * ROWB + koff);
#pragma unroll
            for (int mf = 0; mf < 2; mf++)
#pragma unroll
                for (int nf = 0; nf < 8; nf++)
                    mma16816(acc[mf][nf], aq[mf], &bq[(nf >> 1) * 4 + (nf & 1) * 2]);
        }
    }
}

// ---------------- batched projection GEMMs (7 problems, split-bf16 out) ----------------
struct GemmB {
    const __nv_bfloat16 *Ah[7], *Al[7], *Bh[7], *Bl[7];
    const float* bias[7];
    __nv_bfloat16 *Oh[7], *Ol[7];
    int mode[7];   // 0 = QK scatter [bh][l][192], 1 = V transpose [bh][d][l]
    int part[7];
};

__global__ __launch_bounds__(256, 2)
void gemm_batch(GemmB args)
{
    extern __shared__ char smem[];
    const uint32_t sbase = smem_u32(smem);
    const int z = blockIdx.z;
    const int tid = threadIdx.x;
    const int wid = tid >> 5, lane = tid & 31;
    const int m0 = blockIdx.y * 128, n0 = blockIdx.x * 128;
    const int wm = wid & 3, wn = wid >> 2;

    float acc[2][8][4];
#pragma unroll
    for (int mf = 0; mf < 2; mf++)
#pragma unroll
        for (int nf = 0; nf < 8; nf++)
#pragma unroll
            for (int q = 0; q < 4; q++) acc[mf][nf][q] = 0.f;

    gemm_core(sbase, m0, n0, tid, wm, wn, lane,
              args.Ah[z], args.Al[z], args.Bh[z], args.Bl[z], acc);

    const float* bias = args.bias[z];
    __nv_bfloat16* Oh = args.Oh[z];
    __nv_bfloat16* Ol = args.Ol[z];
    const int mode = args.mode[z], part = args.part[z];

    const int g = lane >> 2, tq = lane & 3;
    float2 bv[8];
#pragma unroll
    for (int nf = 0; nf < 8; nf++)
        bv[nf] = *(const float2*)(bias + n0 + wn * 64 + nf * 8 + 2 * tq);

#pragma unroll
    for (int mf = 0; mf < 2; mf++) {
#pragma unroll
        for (int half = 0; half < 2; half++) {
            const int m = m0 + wm * 32 + mf * 16 + g + half * 8;
            const int bb = m >> 9, ll = m & 511;
#pragma unroll
            for (int nf = 0; nf < 8; nf++) {
                const int n = n0 + wn * 64 + nf * 8 + 2 * tq;
                const int h = n >> 6, dd = n & 63;
                float vx = acc[mf][nf][half * 2 + 0] + bv[nf].x;
                float vy = acc[mf][nf][half * 2 + 1] + bv[nf].y;
                __nv_bfloat16 hx = __float2bfloat16(vx), hy = __float2bfloat16(vy);
                __nv_bfloat16 lx = __float2bfloat16(vx - __bfloat162float(hx));
                __nv_bfloat16 ly = __float2bfloat16(vy - __bfloat162float(hy));
                if (mode == 0) {
                    size_t dst = ((((size_t)bb * NH_ + h) * L_ + ll) * DCAT)
                               + (size_t)part * 64 + dd;
                    __nv_bfloat162 hi2{hx, hy}, lo2{lx, ly};
                    *(__nv_bfloat162*)(Oh + dst) = hi2;
                    *(__nv_bfloat162*)(Ol + dst) = lo2;
                } else {
                    size_t dst = (((size_t)bb * NH_ + h) * HD_ + dd) * L_ + ll;
                    Oh[dst] = hx;  Ol[dst] = lx;
                    Oh[dst + L_] = hy;  Ol[dst + L_] = ly;
                }
            }
        }
    }
}

// ---------------- output projection GEMM (fp32 out) ----------------
__global__ __launch_bounds__(256, 2)
void gemm_out(const __nv_bfloat16* __restrict__ Ah, const __nv_bfloat16* __restrict__ Al,
              const __nv_bfloat16* __restrict__ Bh, const __nv_bfloat16* __restrict__ Bl,
              const float* __restrict__ bias, float* __restrict__ out)
{
    extern __shared__ char smem[];
    const uint32_t sbase = smem_u32(smem);
    const int tid = threadIdx.x;
    const int wid = tid >> 5, lane = tid & 31;
    const int m0 = blockIdx.y * 128, n0 = blockIdx.x * 128;
    const int wm = wid & 3, wn = wid >> 2;

    float acc[2][8][4];
#pragma unroll
    for (int mf = 0; mf < 2; mf++)
#pragma unroll
        for (int nf = 0; nf < 8; nf++)
#pragma unroll
            for (int q = 0; q < 4; q++) acc[mf][nf][q] = 0.f;

    gemm_core(sbase, m0, n0, tid, wm, wn, lane, Ah, Al, Bh, Bl, acc);

    const int g = lane >> 2, tq = lane & 3;
    float2 bv[8];
#pragma unroll
    for (int nf = 0; nf < 8; nf++)
        bv[nf] = *(const float2*)(bias + n0 + wn * 64 + nf * 8 + 2 * tq);
#pragma unroll
    for (int mf = 0; mf < 2; mf++)
#pragma unroll
        for (int half = 0; half < 2; half++) {
            const int m = m0 + wm * 32 + mf * 16 + g + half * 8;
#pragma unroll
            for (int nf = 0; nf < 8; nf++) {
                const int n = n0 + wn * 64 + nf * 8 + 2 * tq;
                float2 v;
                v.x = acc[mf][nf][half * 2 + 0] + bv[nf].x;
                v.y = acc[mf][nf][half * 2 + 1] + bv[nf].y;
                *(float2*)(out + (size_t)m * HID_ + n) = v;
            }
        }
}

// ---------------- flash attention via mma.sync ----------------
// CTA: 128 q-rows, 8 warps x 16 rows. k tiles of 64. Split-bf16 QK (3 prod) + PV (3 prod).
#define AQ_STRIDE 400u      // Q/K smem row bytes (192 bf16 = 384B + 16 pad)
#define AV_STRIDE 144u      // Vt smem row bytes (64 bf16 = 128B + 16 pad)
#define SM_QH 0u
#define SM_QL 51200u
#define SM_KH 102400u
#define SM_KL 128000u
#define SM_VH 153600u
#define SM_VL 162816u
#define ATT_SMEM 172032

__global__ __launch_bounds__(256, 1)
void attn_mma(const float* __restrict__ rel,
              const __nv_bfloat16* __restrict__ Qh, const __nv_bfloat16* __restrict__ Ql,
              const __nv_bfloat16* __restrict__ Kh, const __nv_bfloat16* __restrict__ Kl,
              const __nv_bfloat16* __restrict__ Vth, const __nv_bfloat16* __restrict__ Vtl,
              __nv_bfloat16* __restrict__ Oh, __nv_bfloat16* __restrict__ Ol)
{
    extern __shared__ char smc[];
    const uint32_t sb = smem_u32(smc);
    const int qt = blockIdx.x, bh = blockIdx.y;
    const int q0 = qt * 128;
    const int tid = threadIdx.x, wid = tid >> 5, lane = tid & 31;
    const int g = lane >> 2, tq = lane & 3;
    const int wrow = wid * 16;

    const __nv_bfloat16* qh_g = Qh  + (size_t)bh * L_ * DCAT;
    const __nv_bfloat16* ql_g = Ql  + (size_t)bh * L_ * DCAT;
    const __nv_bfloat16* kh_g = Kh  + (size_t)bh * L_ * DCAT;
    const __nv_bfloat16* kl_g = Kl  + (size_t)bh * L_ * DCAT;
    const __nv_bfloat16* vh_g = Vth + (size_t)bh * HD_ * L_;
    const __nv_bfloat16* vl_g = Vtl + (size_t)bh * HD_ * L_;
    const float* relg = rel + (size_t)bh * L_ * L_;

    // load Q tile (hi+lo): 128 rows x 24 segs x 2 = 6144 cp16
#pragma unroll
    for (int i = 0; i < 24; i++) {
        int idx = i * 256 + tid;
        int mat = idx >= 3072;
        int j = idx - mat * 3072;
        int r = j / 24, s2 = j % 24;
        cp16(sb + (mat ? SM_QL : SM_QH) + r * AQ_STRIDE + s2 * 16,
             (mat ? ql_g : qh_g) + (size_t)(q0 + r) * DCAT + s2 * 8);
    }
    asm volatile("cp.async.commit_group;");

    float m_i[2] = {-3.0e38f, -3.0e38f};
    float l_i[2] = {0.f, 0.f};
    float oacc[8][4];
#pragma unroll
    for (int nf = 0; nf < 8; nf++)
#pragma unroll
        for (int q = 0; q < 4; q++) oacc[nf][q] = 0.f;

    const uint32_t aoffQ = (uint32_t)(wrow + (lane & 7) + ((lane >> 3) & 1) * 8) * AQ_STRIDE
                         + (lane >> 4) * 16;
    const uint32_t boffK = (uint32_t)((lane & 7) + ((lane >> 4) & 1) * 8) * AQ_STRIDE
                         + ((lane >> 3) & 1) * 16;
    const uint32_t boffV = (uint32_t)((lane & 7) + ((lane >> 4) & 1) * 8) * AV_STRIDE
                         + ((lane >> 3) & 1) * 16;

    const int ntiles = qt * 2 + 2;
    for (int kt = 0; kt < ntiles; kt++) {
        const int k0 = kt * 64;
        __syncthreads();   // previous tile's smem reads done
        // load K (hi+lo) + Vt (hi+lo): 3072 + 1024 segs
#pragma unroll
        for (int i = 0; i < 16; i++) {
            int idx = i * 256 + tid;
            if (idx < 3072) {
                int mat = idx >= 1536;
                int j = idx - mat * 1536;
                int r = j / 24, s2 = j % 24;
                cp16(sb + (mat ? SM_KL : SM_KH) + r * AQ_STRIDE + s2 * 16,
                     (mat ? kl_g : kh_g) + (size_t)(k0 + r) * DCAT + s2 * 8);
            } else {
                int j = idx - 3072;
                int mat = j >= 512;
                j -= mat * 512;
                int d = j / 8, s2 = j % 8;
                cp16(sb + (mat ? SM_VL : SM_VH) + d * AV_STRIDE + s2 * 16,
                     (mat ? vl_g : vh_g) + (size_t)d * L_ + k0 + s2 * 8);
            }
        }
        asm volatile("cp.async.commit_group;");
        asm volatile("cp.async.wait_group 0;" ::: "memory");
        __syncthreads();

        if (k0 > q0 + wrow + 15) continue;   // warp fully masked: exact no-op

        // ---- S = Qh*Kh + Qh*Kl + Ql*Kh (k-dim 192 each) ----
        float sacc[8][4];
#pragma unroll
        for (int nf = 0; nf < 8; nf++)
#pragma unroll
            for (int q = 0; q < 4; q++) sacc[nf][q] = 0.f;

#pragma unroll
        for (int ks = 0; ks < 12; ks++) {
            const uint32_t koff = ks * 32;
            uint32_t aqh[4], aql[4], bqh[16], bql[16];
            ldm_x4(aqh, sb + SM_QH + aoffQ + koff);
            ldm_x4(aql, sb + SM_QL + aoffQ + koff);
#pragma unroll
            for (int np = 0; np < 4; np++) {
                ldm_x4(&bqh[np * 4], sb + SM_KH + boffK + np * 16 * AQ_STRIDE + koff);
                ldm_x4(&bql[np * 4], sb + SM_KL + boffK + np * 16 * AQ_STRIDE + koff);
            }
#pragma unroll
            for (int nf = 0; nf < 8; nf++) {
                const uint32_t* bh_ = &bqh[(nf >> 1) * 4 + (nf & 1) * 2];
                const uint32_t* bl_ = &bql[(nf >> 1) * 4 + (nf & 1) * 2];
                mma16816(sacc[nf], aqh, bh_);
                mma16816(sacc[nf], aqh, bl_);
                mma16816(sacc[nf], aql, bh_);
            }
        }

        // ---- bias + mask + online softmax ----
        const int row0 = q0 + wrow + g;
        const int row1 = row0 + 8;
        const bool diag = (k0 + 63 > q0 + wrow);
        float pmax0 = -3.0e38f, pmax1 = -3.0e38f;
#pragma unroll
        for (int nf = 0; nf < 8; nf++) {
            const int col = k0 + nf * 8 + 2 * tq;
            float2 r0 = *(const float2*)(relg + (size_t)row0 * L_ + col);
            float2 r1 = *(const float2*)(relg + (size_t)row1 * L_ + col);
            float s0 = fmaf(sacc[nf][0], 0.125f, r0.x);
            float s1 = fmaf(sacc[nf][1], 0.125f, r0.y);
            float s2 = fmaf(sacc[nf][2], 0.125f, r1.x);
            float s3 = fmaf(sacc[nf][3], 0.125f, r1.y);
            if (diag) {
                if (col     > row0) s0 = -3.0e38f;
                if (col + 1 > row0) s1 = -3.0e38f;
                if (col     > row1) s2 = -3.0e38f;
                if (col + 1 > row1) s3 = -3.0e38f;
            }
            sacc[nf][0] = s0; sacc[nf][1] = s1; sacc[nf][2] = s2; sacc[nf][3] = s3;
            pmax0 = fmaxf(pmax0, fmaxf(s0, s1));
            pmax1 = fmaxf(pmax1, fmaxf(s2, s3));
        }
#pragma unroll
        for (int d = 1; d < 4; d <<= 1) {
            pmax0 = fmaxf(pmax0, __shfl_xor_sync(0xffffffffu, pmax0, d));
            pmax1 = fmaxf(pmax1, __shfl_xor_sync(0xffffffffu, pmax1, d));
        }
        const float nm0 = fmaxf(m_i[0], pmax0);
        const float nm1 = fmaxf(m_i[1], pmax1);
        const float al0 = __expf(m_i[0] - nm0);
        const float al1 = __expf(m_i[1] - nm1);
        float rs0 = 0.f, rs1 = 0.f;
#pragma unroll
        for (int nf = 0; nf < 8; nf++) {
            sacc[nf][0] = __expf(sacc[nf][0] - nm0);
            sacc[nf][1] = __expf(sacc[nf][1] - nm0);
            sacc[nf][2] = __expf(sacc[nf][2] - nm1);
            sacc[nf][3] = __expf(sacc[nf][3] - nm1);
            rs0 += sacc[nf][0] + sacc[nf][1];
            rs1 += sacc[nf][2] + sacc[nf][3];
        }
#pragma unroll
        for (int d = 1; d < 4; d <<= 1) {
            rs0 += __shfl_xor_sync(0xffffffffu, rs0, d);
            rs1 += __shfl_xor_sync(0xffffffffu, rs1, d);
        }
        l_i[0] = l_i[0] * al0 + rs0;  m_i[0] = nm0;
        l_i[1] = l_i[1] * al1 + rs1;  m_i[1] = nm1;
#pragma unroll
        for (int nf = 0; nf < 8; nf++) {
            oacc[nf][0] *= al0; oacc[nf][1] *= al0;
            oacc[nf][2] *= al1; oacc[nf][3] *= al1;
        }

        // ---- O += (Ph+Pl) @ (Vh+Vl) over k=64 ----
#pragma unroll
        for (int ks = 0; ks < 4; ks++) {
            uint32_t afh[4], afl[4];
            {
                float p00 = sacc[2*ks][0],   p01 = sacc[2*ks][1];
                float p02 = sacc[2*ks][2],   p03 = sacc[2*ks][3];
                float p10 = sacc[2*ks+1][0], p11 = sacc[2*ks+1][1];
                float p12 = sacc[2*ks+1][2], p13 = sacc[2*ks+1][3];
                afh[0] = pack_bf2(p00, p01);
                afh[1] = pack_bf2(p02, p03);
                afh[2] = pack_bf2(p10, p11);
                afh[3] = pack_bf2(p12, p13);
                __nv_bfloat162 h0 = *(__nv_bfloat162*)&afh[0];
                __nv_bfloat162 h1 = *(__nv_bfloat162*)&afh[1];
                __nv_bfloat162 h2 = *(__nv_bfloat162*)&afh[2];
                __nv_bfloat162 h3 = *(__nv_bfloat162*)&afh[3];
                afl[0] = pack_bf2(p00 - __bfloat162float(h0.x), p01 - __bfloat162float(h0.y));
                afl[1] = pack_bf2(p02 - __bfloat162float(h1.x), p03 - __bfloat162float(h1.y));
                afl[2] = pack_bf2(p10 - __bfloat162float(h2.x), p11 - __bfloat162float(h2.y));
                afl[3] = pack_bf2(p12 - __bfloat162float(h3.x), p13 - __bfloat162float(h3.y));
            }
            uint32_t bvh[16], bvl[16];
            const uint32_t koff = ks * 32;
#pragma unroll
            for (int np = 0; np < 4; np++) {
                ldm_x4(&bvh[np * 4], sb + SM_VH + boffV + np * 16 * AV_STRIDE + koff);
                ldm_x4(&bvl[np * 4], sb + SM_VL + boffV + np * 16 * AV_STRIDE + koff);
            }
#pragma unroll
            for (int nf = 0; nf < 8; nf++) {
                const uint32_t* bh_ = &bvh[(nf >> 1) * 4 + (nf & 1) * 2];
                const uint32_t* bl_ = &bvl[(nf >> 1) * 4 + (nf & 1) * 2];
                mma16816(oacc[nf], afh, bh_);
                mma16816(oacc[nf], afh, bl_);
                mma16816(oacc[nf], afl, bh_);
            }
        }
    }

    // ---- epilogue: normalize, split-bf16 write to [m][HID] ----
    const int b = bh >> 4, h = bh & 15;
    const float inv0 = 1.0f / l_i[0];
    const float inv1 = 1.0f / l_i[1];
    const size_t m0g = (size_t)(b * L_ + q0 + wrow + g) * HID_;
    const size_t m1g = m0g + 8 * HID_;
#pragma unroll
    for (int nf = 0; nf < 8; nf++) {
        const int col = h * 64 + nf * 8 + 2 * tq;
        float v0 = oacc[nf][0] * inv0, v1 = oacc[nf][1] * inv0;
        float v2 = oacc[nf][2] * inv1, v3 = oacc[nf][3] * inv1;
        __nv_bfloat162 hi0, lo0, hi1, lo1;
        hi0.x = __float2bfloat16(v0); hi0.y = __float2bfloat16(v1);
        lo0.x = __float2bfloat16(v0 - __bfloat162float(hi0.x));
        lo0.y = __float2bfloat16(v1 - __bfloat162float(hi0.y));
        hi1.x = __float2bfloat16(v2); hi1.y = __float2bfloat16(v3);
        lo1.x = __float2bfloat16(v2 - __bfloat162float(hi1.x));
        lo1.y = __float2bfloat16(v3 - __bfloat162float(hi1.y));
        *(__nv_bfloat162*)(Oh + m0g + col) = hi0;
        *(__nv_bfloat162*)(Ol + m0g + col) = lo0;
        *(__nv_bfloat162*)(Oh + m1g + col) = hi1;
        *(__nv_bfloat162*)(Ol + m1g + col) = lo1;
    }
}

// ---------------- launcher ----------------
extern "C" void kernel_launch(void* const* d_in, const int* in_sizes, int n_in,
                              void* d_out, int out_size)
{
    const float* rel = (const float*)d_in[5];
    float* out = (float*)d_out;

    __nv_bfloat16 *xh, *xl, *wh, *wl, *qh, *ql, *kh, *kl, *vth, *vtl;
    cudaGetSymbolAddress((void**)&xh, g_xh);
    cudaGetSymbolAddress((void**)&xl, g_xl);
    cudaGetSymbolAddress((void**)&wh, g_wh);
    cudaGetSymbolAddress((void**)&wl, g_wl);
    cudaGetSymbolAddress((void**)&qh, g_qh);
    cudaGetSymbolAddress((void**)&ql, g_ql);
    cudaGetSymbolAddress((void**)&kh, g_kh);
    cudaGetSymbolAddress((void**)&kl, g_kl);
    cudaGetSymbolAddress((void**)&vth, g_vth);
    cudaGetSymbolAddress((void**)&vtl, g_vtl);

    cudaFuncSetAttribute(gemm_batch, cudaFuncAttributeMaxDynamicSharedMemorySize, GEMM_SMEM);
    cudaFuncSetAttribute(gemm_out, cudaFuncAttributeMaxDynamicSharedMemorySize, GEMM_SMEM);
    cudaFuncSetAttribute(attn_mma, cudaFuncAttributeMaxDynamicSharedMemorySize, ATT_SMEM);

    const int n4 = (int)(XN / 4);

    // split 4 activations (batched)
    SplitSrc ss;
    ss.p[0] = (const float*)d_in[0];  // seq_id
    ss.p[1] = (const float*)d_in[1];  // seq_cate
    ss.p[2] = (const float*)d_in[2];  // seq_pos
    ss.p[3] = (const float*)d_in[3];  // V_id_input
    split_b<<<dim3((n4 + 255) / 256, 4), 256>>>(ss, xh, xl, n4);

    // transpose+split 8 weights (batched)  slots: 0=q_id 1=k_id 2=v_id 3=q_cate 4=k_cate 5=q_pos 6=k_pos 7=out
    WSrc ws;
    ws.p[0] = (const float*)d_in[6];   ws.p[1] = (const float*)d_in[8];
    ws.p[2] = (const float*)d_in[10];  ws.p[3] = (const float*)d_in[12];
    ws.p[4] = (const float*)d_in[14];  ws.p[5] = (const float*)d_in[16];
    ws.p[6] = (const float*)d_in[18];  ws.p[7] = (const float*)d_in[20];
    splitT_b<<<dim3(32, 32, 8), dim3(32, 8)>>>(ws, wh, wl);

    // 7 projection GEMMs in one launch
    GemmB gb;
    const int ain[7]  = {0, 1, 2, 0, 1, 2, 3};
    const int wsl[7]  = {0, 3, 5, 1, 4, 6, 2};
    const int bidx[7] = {7, 13, 17, 9, 15, 19, 11};
    for (int z = 0; z < 7; z++) {
        gb.Ah[z] = xh + (size_t)ain[z] * XN;
        gb.Al[z] = xl + (size_t)ain[z] * XN;
        gb.Bh[z] = wh + (size_t)wsl[z] * WN;
        gb.Bl[z] = wl + (size_t)wsl[z] * WN;
        gb.bias[z] = (const float*)d_in[bidx[z]];
    }
    gb.Oh[0] = qh;  gb.Ol[0] = ql;  gb.mode[0] = 0; gb.part[0] = 0;
    gb.Oh[1] = qh;  gb.Ol[1] = ql;  gb.mode[1] = 0; gb.part[1] = 1;
    gb.Oh[2] = qh;  gb.Ol[2] = ql;  gb.mode[2] = 0; gb.part[2] = 2;
    gb.Oh[3] = kh;  gb.Ol[3] = kl;  gb.mode[3] = 0; gb.part[3] = 0;
    gb.Oh[4] = kh;  gb.Ol[4] = kl;  gb.mode[4] = 0; gb.part[4] = 1;
    gb.Oh[5] = kh;  gb.Ol[5] = kl;  gb.mode[5] = 0; gb.part[5] = 2;
    gb.Oh[6] = vth; gb.Ol[6] = vtl; gb.mode[6] = 1; gb.part[6] = 0;
    gemm_batch<<<dim3(8, 64, 7), 256, GEMM_SMEM>>>(gb);

    // attention (writes split-bf16 out-proj input into xh/xl slot 4)
    attn_mma<<<dim3(4, 256), 256, ATT_SMEM>>>(rel, qh, ql, kh, kl, vth, vtl,
                                              xh + 4 * XN, xl + 4 * XN);

    // output projection
    gemm_out<<<dim3(8, 64), 256, GEMM_SMEM>>>(xh + 4 * XN, xl + 4 * XN,
                                              wh + 7 * WN, wl + 7 * WN,
                                              (const float*)d_in[21], out);
}